// round 6
// baseline (speedup 1.0000x reference)
#include <cuda_runtime.h>
#include <cstdint>

#define CB 32
#define CC 256
#define CH 56
#define CW 56
#define HP 58
#define WP 58
#define WPIX (HP*WP)          // 3364 padded positions per image
#define NPIX (CB*CH*CW)       // 100352 output pixels
#define TILES 26              // 26*128 = 3328 > last valid q (55*58+55 = 3245)
#define KSTAGES 36            // 9 taps * 4 chunks of 64 channels

typedef unsigned short ushort_t;

// ---------------- scratch (device globals; no allocation) ----------------
__device__ __align__(128) ushort_t g_xq[(size_t)CB*WPIX*CC + 131072]; // bf16 ±1/0 padded NHWC + tail slack
__device__ __align__(128) ushort_t g_wq[9*CC*CC];                     // bf16 sign weights [tap][o][i]
__device__ float  g_alpha[CC];
__device__ __align__(16) float g_acc[(size_t)NPIX*CC];                // [b][h][w][o] f32 (exact ints)
__device__ long long          g_sum[CC];
__device__ unsigned long long g_sumsq[CC];
__device__ float g_scale[CC], g_shift[CC];

// ---------------- helpers ----------------
__device__ __forceinline__ void cpa16(uint32_t dst, const void* src) {
    asm volatile("cp.async.cg.shared.global [%0], [%1], 16;\n" :: "r"(dst), "l"(src));
}
__device__ __forceinline__ void ldm4(uint32_t addr, unsigned &r0, unsigned &r1,
                                     unsigned &r2, unsigned &r3) {
    asm volatile("ldmatrix.sync.aligned.m8n8.x4.shared.b16 {%0,%1,%2,%3}, [%4];\n"
        : "=r"(r0), "=r"(r1), "=r"(r2), "=r"(r3) : "r"(addr));
}
__device__ __forceinline__ void hmma(float* c, const unsigned* a, unsigned b0, unsigned b1) {
    asm volatile("mma.sync.aligned.m16n8k16.row.col.f32.bf16.bf16.f32 "
        "{%0,%1,%2,%3}, {%4,%5,%6,%7}, {%8,%9}, {%0,%1,%2,%3};\n"
        : "+f"(c[0]), "+f"(c[1]), "+f"(c[2]), "+f"(c[3])
        : "r"(a[0]), "r"(a[1]), "r"(a[2]), "r"(a[3]), "r"(b0), "r"(b1));
}
// swizzle for 128B rows: 8 x 16B chunks, chunk' = chunk ^ (row&7)
__device__ __forceinline__ uint32_t swz128(int row, int c) {
    return (uint32_t)(row * 128 + ((c ^ (row & 7)) * 16));
}

// ---------------- 1) zero halo + slack of padded activation buffer ----------------
// Interior is fully rewritten by k_pack each call; only the 228 halo positions
// per image (rows h=0,57 and cols w=0,57) and the tail slack need zeros.
__global__ void k_zero_halo() {
    int idx = blockIdx.x * blockDim.x + threadIdx.x;
    const int HALO = 228;                       // per image
    const int NHALO = HALO * CB * 32;           // 32 vec16 per position (256 ch)
    if (idx < NHALO) {
        int vec = idx & 31;                     // 8-channel group
        int pid = idx >> 5;
        int img = pid / HALO, r = pid % HALO;
        int q;
        if (r < 58) q = r;                      // top row
        else if (r < 116) q = 57 * WP + (r - 58); // bottom row
        else { int rr = r - 116; q = (1 + (rr >> 1)) * WP + ((rr & 1) * 57); }
        *(int4*)(g_xq + ((size_t)img * WPIX + q) * CC + vec * 8) = make_int4(0, 0, 0, 0);
    } else {
        int j = idx - NHALO;
        if (j < 131072 / 8)
            *(int4*)(g_xq + (size_t)CB * WPIX * CC + j * 8) = make_int4(0, 0, 0, 0);
    }
}

// ---------------- 2) binarize + NCHW -> padded NHWC bf16 ----------------
__global__ void k_pack(const float* __restrict__ x) {
    int bh = blockIdx.x; int b = bh / CH, h = bh % CH;
    int ic = blockIdx.y;                                  // 32-channel chunk
    __shared__ ushort_t tile[32][65];
    int tx = threadIdx.x & 31, ty = threadIdx.x >> 5;     // ty 0..7
    const float* xp = x + (((size_t)(b * CC + ic * 32) * CH) + h) * CW;
    #pragma unroll
    for (int ii = 0; ii < 4; ii++) {
        int il = ty * 4 + ii;
        const float* row = xp + (size_t)il * CH * CW;
        #pragma unroll
        for (int wc2 = 0; wc2 < 2; wc2++) {
            int w = wc2 * 32 + tx;
            if (w < CW) tile[il][w] = (row[w] >= 0.f) ? (ushort_t)0x3F80 : (ushort_t)0xBF80;
        }
    }
    __syncthreads();
    ushort_t* dst0 = g_xq + ((size_t)(b * HP + h + 1) * WP + 1) * CC + ic * 32 + tx;
    for (int w = ty; w < CW; w += 8)
        dst0[(size_t)w * CC] = tile[tx][w];
}

// ---------------- 3) weight prep (+ stats zero) ----------------
__global__ void k_prep_weights(const float* __restrict__ w) {
    int o = blockIdx.x, t = threadIdx.x;          // t = input channel i
    __shared__ float red[256];
    if (t == 0) { g_sum[o] = 0; g_sumsq[o] = 0; }
    const float* wo = w + (size_t)o * CC * 9;
    float wv[9];
    #pragma unroll
    for (int tap = 0; tap < 9; tap++) wv[tap] = wo[t * 9 + tap];
    float absacc = 0.f;
    #pragma unroll
    for (int tap = 0; tap < 9; tap++) {
        red[t] = wv[tap]; __syncthreads();
        for (int s = 128; s > 0; s >>= 1) { if (t < s) red[t] += red[t + s]; __syncthreads(); }
        float m = red[0] * (1.0f / 256.0f);
        __syncthreads();
        float wc = wv[tap] - m;
        wc = fminf(1.f, fmaxf(-1.f, wc));
        absacc += fabsf(wc);
        g_wq[((size_t)tap * CC + o) * CC + t] = (wc >= 0.f) ? (ushort_t)0x3F80 : (ushort_t)0xBF80;
    }
    red[t] = absacc; __syncthreads();
    for (int s = 128; s > 0; s >>= 1) { if (t < s) red[t] += red[t + s]; __syncthreads(); }
    if (t == 0) g_alpha[o] = red[0] * (1.0f / 2304.0f);
}

// ---------------- 4) conv: bf16 mma.sync implicit GEMM, 2 CTAs/SM ----------------
// CTA: M=128 padded positions x N=128 cout, K=2304 (36 stages of 64 channels).
// Warp tile 64x32 (2x4 warp grid). smem: A 3x16KB at [0,48K), B 3x16KB at [48K,96K).
__global__ void __launch_bounds__(256, 2) k_conv() {
    extern __shared__ __align__(128) char sm[];
    uint32_t sbase = (uint32_t)__cvta_generic_to_shared(sm);
    int tid = threadIdx.x;
    int warp = tid >> 5, lane = tid & 31;
    int wm = warp & 1, wn = warp >> 1;                 // 2(M) x 4(N) warp grid
    int img = blockIdx.x / TILES, tile = blockIdx.x % TILES;
    int q0 = tile * 128;
    int n0 = blockIdx.y * 128;

    // cp.async per-thread setup: row = tid>>1, 4 x 16B chunks
    int ar = tid >> 1, ac0 = (tid & 1) * 4;
    const ushort_t* gA = g_xq + ((size_t)img * WPIX + q0 + ar) * CC + ac0 * 8;
    const ushort_t* gB = g_wq + (size_t)(n0 + ar) * CC + ac0 * 8;
    uint32_t adst[4], bdst[4];
    #pragma unroll
    for (int j = 0; j < 4; j++) {
        adst[j] = swz128(ar, ac0 + j);
        bdst[j] = 49152 + swz128(ar, ac0 + j);
    }

    auto issue = [&](int s) {
        int tap = s >> 2, kc = s & 3;
        int dh = tap / 3, dw = tap - dh * 3;
        int buf = s % 3;
        const ushort_t* a = gA + (dh * WP + dw) * CC + kc * 64;
        uint32_t ab = sbase + buf * 16384;
        #pragma unroll
        for (int j = 0; j < 4; j++) cpa16(ab + adst[j], a + j * 8);
        const ushort_t* b = gB + (size_t)tap * CC * CC + kc * 64;
        uint32_t bb = sbase + buf * 16384;
        #pragma unroll
        for (int j = 0; j < 4; j++) cpa16(bb + bdst[j], b + j * 8);
        asm volatile("cp.async.commit_group;" ::: "memory");
    };

    // ldmatrix per-thread bases
    int t8 = lane >> 3, r8 = lane & 7;
    int rowA = wm * 64 + (t8 & 1) * 8 + r8;
    int rowB = wn * 32 + (t8 & 1) * 8 + r8;
    int chalf = t8 >> 1;
    uint32_t a0[4], b0[4];
    #pragma unroll
    for (int kk = 0; kk < 4; kk++) {
        a0[kk] = swz128(rowA, kk * 2 + chalf);
        b0[kk] = 49152 + swz128(rowB, kk * 2 + chalf);
    }

    float acc[4][4][4];
    #pragma unroll
    for (int i = 0; i < 4; i++)
        #pragma unroll
        for (int j = 0; j < 4; j++)
            #pragma unroll
            for (int k = 0; k < 4; k++) acc[i][j][k] = 0.f;

    issue(0); issue(1);

    #pragma unroll 1
    for (int s = 0; s < KSTAGES; s++) {
        asm volatile("cp.async.wait_group 1;" ::: "memory");
        __syncthreads();
        if (s + 2 < KSTAGES) issue(s + 2);
        else asm volatile("cp.async.commit_group;" ::: "memory");

        int buf = s % 3;
        uint32_t Sb = sbase + buf * 16384;
        #pragma unroll
        for (int kk = 0; kk < 4; kk++) {
            unsigned af[4][4], bf[2][4];
            #pragma unroll
            for (int mt = 0; mt < 4; mt++)
                ldm4(Sb + a0[kk] + mt * 2048, af[mt][0], af[mt][1], af[mt][2], af[mt][3]);
            #pragma unroll
            for (int nb = 0; nb < 2; nb++)
                ldm4(Sb + b0[kk] + nb * 2048, bf[nb][0], bf[nb][1], bf[nb][2], bf[nb][3]);
            #pragma unroll
            for (int mt = 0; mt < 4; mt++) {
                hmma(acc[mt][0], af[mt], bf[0][0], bf[0][2]);
                hmma(acc[mt][1], af[mt], bf[0][1], bf[0][3]);
                hmma(acc[mt][2], af[mt], bf[1][0], bf[1][2]);
                hmma(acc[mt][3], af[mt], bf[1][1], bf[1][3]);
            }
        }
    }

    // ---------------- epilogue: store + fused per-channel stats ----------------
    int g = lane >> 2, t4 = lane & 3;
    float* p1[4]; float* p2[4]; bool v1[4], v2[4];
    #pragma unroll
    for (int mt = 0; mt < 4; mt++) {
        int m = wm * 64 + mt * 16 + g;
        int q = q0 + m;
        int hh = q / WP, ww = q - hh * WP;
        v1[mt] = (hh < CH) && (ww < CW);
        p1[mt] = g_acc + ((size_t)((img * CH + (v1[mt] ? hh : 0)) * CW + (v1[mt] ? ww : 0))) * CC + n0;
        int q2 = q + 8;
        int hh2 = q2 / WP, ww2 = q2 - hh2 * WP;
        v2[mt] = (hh2 < CH) && (ww2 < CW);
        p2[mt] = g_acc + ((size_t)((img * CH + (v2[mt] ? hh2 : 0)) * CW + (v2[mt] ? ww2 : 0))) * CC + n0;
    }

    // smem overlay for CTA-level reduction (stage-0 A region, reads long done)
    int* red_s = (int*)sm;            // [2][128]
    int* red_q = (int*)sm + 256;      // [2][128]

    #pragma unroll
    for (int nt = 0; nt < 4; nt++) {
        int n = wn * 32 + nt * 8 + t4 * 2;
        int s0 = 0, s1 = 0; unsigned u0 = 0, u1 = 0;
        #pragma unroll
        for (int mt = 0; mt < 4; mt++) {
            float c0 = acc[mt][nt][0], c1 = acc[mt][nt][1];
            float c2 = acc[mt][nt][2], c3 = acc[mt][nt][3];
            if (v1[mt]) {
                *(float2*)(p1[mt] + n) = make_float2(c0, c1);
                int i0 = (int)c0, i1 = (int)c1;
                s0 += i0; u0 += (unsigned)(i0 * i0);
                s1 += i1; u1 += (unsigned)(i1 * i1);
            }
            if (v2[mt]) {
                *(float2*)(p2[mt] + n) = make_float2(c2, c3);
                int i2 = (int)c2, i3 = (int)c3;
                s0 += i2; u0 += (unsigned)(i2 * i2);
                s1 += i3; u1 += (unsigned)(i3 * i3);
            }
        }
        #pragma unroll
        for (int off = 4; off < 32; off <<= 1) {
            s0 += __shfl_xor_sync(0xffffffffu, s0, off);
            s1 += __shfl_xor_sync(0xffffffffu, s1, off);
            u0 += __shfl_xor_sync(0xffffffffu, u0, off);
            u1 += __shfl_xor_sync(0xffffffffu, u1, off);
        }
        if (g == 0) {
            red_s[wm * 128 + n] = s0;      red_s[wm * 128 + n + 1] = s1;
            red_q[wm * 128 + n] = (int)u0; red_q[wm * 128 + n + 1] = (int)u1;
        }
    }
    __syncthreads();
    if (tid < 128) {
        long long ts = (long long)red_s[tid] + (long long)red_s[128 + tid];
        long long tq = (long long)(unsigned)red_q[tid] + (long long)(unsigned)red_q[128 + tid];
        atomicAdd((unsigned long long*)&g_sum[n0 + tid], (unsigned long long)ts);
        atomicAdd(&g_sumsq[n0 + tid], (unsigned long long)tq);
    }
}

// ---------------- 5) per-channel scale/shift ----------------
__global__ void k_finalize(const float* __restrict__ gamma, const float* __restrict__ beta) {
    int o = threadIdx.x;
    double N = (double)NPIX;
    double mean = (double)g_sum[o] / N;
    double ex2  = (double)g_sumsq[o] / N;
    double var  = ex2 - mean * mean;
    double a    = (double)g_alpha[o];
    double inv  = 1.0 / sqrt(a * a * var + 1e-5);
    double sc   = (double)gamma[o] * a * inv;
    g_scale[o] = (float)sc;
    g_shift[o] = (float)((double)beta[o] - sc * mean);
}

// ---------------- 6) affine + relu + NHWC -> NCHW ----------------
__global__ void k_epilogue(float* __restrict__ out) {
    __shared__ float tile[64][57];
    int bh = blockIdx.x, oc = blockIdx.y;
    int b = bh / CH, h = bh % CH;
    const float* accp = g_acc + (size_t)bh * CW * CC + oc * 64;
    int t = threadIdx.x;
    int ol = t & 63, wq = t >> 6;
    float sc = g_scale[oc * 64 + ol], sh = g_shift[oc * 64 + ol];
    for (int w = wq; w < CW; w += 4)
        tile[ol][w] = fmaxf(fmaf(sc, accp[(size_t)w * CC + ol], sh), 0.f);
    __syncthreads();
    float* op = out + ((size_t)(b * CC + oc * 64) * CH + h) * CW;
    for (int idx = t; idx < 64 * CW; idx += 256) {
        int o_l = idx / CW, w = idx - o_l * CW;
        op[(size_t)o_l * CH * CW + w] = tile[o_l][w];
    }
}

// ---------------- launch ----------------
extern "C" void kernel_launch(void* const* d_in, const int* in_sizes, int n_in,
                              void* d_out, int out_size) {
    (void)in_sizes; (void)n_in; (void)out_size;
    const float* x     = (const float*)d_in[0];
    const float* w     = (const float*)d_in[1];
    // d_in[2] = bias: cancels exactly under training-mode BN
    const float* gamma = (const float*)d_in[3];
    const float* beta  = (const float*)d_in[4];
    float* out = (float*)d_out;

    cudaFuncSetAttribute(k_conv, cudaFuncAttributeMaxDynamicSharedMemorySize, 98304);

    int zthreads = 228 * CB * 32 + 131072 / 8;
    k_zero_halo<<<(zthreads + 255) / 256, 256>>>();
    k_pack<<<dim3(CB * CH, 8), 256>>>(x);
    k_prep_weights<<<CC, 256>>>(w);
    k_conv<<<dim3(CB * TILES, 2), 256, 98304>>>();   // 4th launch -> ncu capture slot
    k_finalize<<<1, 256>>>(gamma, beta);
    k_epilogue<<<dim3(CB * CH, 4), 256>>>(out);
}

// round 7
// speedup vs baseline: 1.4014x; 1.4014x over previous
#include <cuda_runtime.h>
#include <cuda_fp16.h>
#include <cstdint>

#define CB 32
#define CC 256
#define CH 56
#define CW 56
#define HP 58
#define WP 58
#define WPIX (HP*WP)          // 3364 padded positions per image
#define NPIX (CB*CH*CW)       // 100352 output pixels
#define TILES 26              // 26*128 = 3328 > last valid q (55*58+55 = 3245)
#define KSTAGES 72            // 9 taps * 8 chunks of 32 channels

typedef unsigned short ushort_t;

// ---------------- scratch (device globals; no allocation) ----------------
__device__ __align__(128) ushort_t g_xq[(size_t)CB*WPIX*CC + 131072]; // fp16 ±1/0 padded NHWC + tail slack
__device__ __align__(128) ushort_t g_wq[9*CC*CC];                     // fp16 sign weights [tap][o][i]
__device__ float  g_alpha[CC];
__device__ __align__(16) float g_acc[(size_t)NPIX*CC];                // [b][h][w][o] f32 (exact ints)
__device__ long long          g_sum[CC];
__device__ unsigned long long g_sumsq[CC];
__device__ float g_scale[CC], g_shift[CC];

#define PONE 0x3C00   // fp16 +1.0
#define NONE 0xBC00   // fp16 -1.0

// ---------------- helpers ----------------
__device__ __forceinline__ void cpa16(uint32_t dst, const void* src) {
    asm volatile("cp.async.cg.shared.global [%0], [%1], 16;\n" :: "r"(dst), "l"(src));
}
__device__ __forceinline__ void ldm4(uint32_t addr, unsigned &r0, unsigned &r1,
                                     unsigned &r2, unsigned &r3) {
    asm volatile("ldmatrix.sync.aligned.m8n8.x4.shared.b16 {%0,%1,%2,%3}, [%4];\n"
        : "=r"(r0), "=r"(r1), "=r"(r2), "=r"(r3) : "r"(addr));
}
// f16-accumulator HMMA: exact for even-integer sums |v| <= 4096
__device__ __forceinline__ void hmma16(unsigned* c, const unsigned* a, unsigned b0, unsigned b1) {
    asm volatile("mma.sync.aligned.m16n8k16.row.col.f16.f16.f16.f16 "
        "{%0,%1}, {%2,%3,%4,%5}, {%6,%7}, {%0,%1};\n"
        : "+r"(c[0]), "+r"(c[1])
        : "r"(a[0]), "r"(a[1]), "r"(a[2]), "r"(a[3]), "r"(b0), "r"(b1));
}
// swizzle for 64B rows: 4 x 16B chunks, chunk' = chunk ^ ((row>>1)&3)
__device__ __forceinline__ uint32_t swz64(int row, int c) {
    return (uint32_t)(row * 64 + ((c ^ ((row >> 1) & 3)) * 16));
}

// ---------------- 1) zero halo + slack of padded activation buffer ----------------
__global__ void k_zero_halo() {
    int idx = blockIdx.x * blockDim.x + threadIdx.x;
    const int HALO = 228;                       // per image
    const int NHALO = HALO * CB * 32;           // 32 vec16 per position (256 ch)
    if (idx < NHALO) {
        int vec = idx & 31;                     // 8-channel group
        int pid = idx >> 5;
        int img = pid / HALO, r = pid % HALO;
        int q;
        if (r < 58) q = r;                        // top row
        else if (r < 116) q = 57 * WP + (r - 58); // bottom row
        else { int rr = r - 116; q = (1 + (rr >> 1)) * WP + ((rr & 1) * 57); }
        *(int4*)(g_xq + ((size_t)img * WPIX + q) * CC + vec * 8) = make_int4(0, 0, 0, 0);
    } else {
        int j = idx - NHALO;
        if (j < 131072 / 8)
            *(int4*)(g_xq + (size_t)CB * WPIX * CC + j * 8) = make_int4(0, 0, 0, 0);
    }
}

// ---------------- 2) binarize + NCHW -> padded NHWC fp16 ----------------
__global__ void k_pack(const float* __restrict__ x) {
    int bh = blockIdx.x; int b = bh / CH, h = bh % CH;
    int ic = blockIdx.y;                                  // 32-channel chunk
    __shared__ ushort_t tile[32][65];
    int tx = threadIdx.x & 31, ty = threadIdx.x >> 5;     // ty 0..7
    const float* xp = x + (((size_t)(b * CC + ic * 32) * CH) + h) * CW;
    #pragma unroll
    for (int ii = 0; ii < 4; ii++) {
        int il = ty * 4 + ii;
        const float* row = xp + (size_t)il * CH * CW;
        #pragma unroll
        for (int wc2 = 0; wc2 < 2; wc2++) {
            int w = wc2 * 32 + tx;
            if (w < CW) tile[il][w] = (row[w] >= 0.f) ? (ushort_t)PONE : (ushort_t)NONE;
        }
    }
    __syncthreads();
    ushort_t* dst0 = g_xq + ((size_t)(b * HP + h + 1) * WP + 1) * CC + ic * 32 + tx;
    for (int w = ty; w < CW; w += 8)
        dst0[(size_t)w * CC] = tile[tx][w];
}

// ---------------- 3) weight prep (+ stats zero) ----------------
__global__ void k_prep_weights(const float* __restrict__ w) {
    int o = blockIdx.x, t = threadIdx.x;          // t = input channel i
    __shared__ float red[256];
    if (t == 0) { g_sum[o] = 0; g_sumsq[o] = 0; }
    const float* wo = w + (size_t)o * CC * 9;
    float wv[9];
    #pragma unroll
    for (int tap = 0; tap < 9; tap++) wv[tap] = wo[t * 9 + tap];
    float absacc = 0.f;
    #pragma unroll
    for (int tap = 0; tap < 9; tap++) {
        red[t] = wv[tap]; __syncthreads();
        for (int s = 128; s > 0; s >>= 1) { if (t < s) red[t] += red[t + s]; __syncthreads(); }
        float m = red[0] * (1.0f / 256.0f);
        __syncthreads();
        float wc = wv[tap] - m;
        wc = fminf(1.f, fmaxf(-1.f, wc));
        absacc += fabsf(wc);
        g_wq[((size_t)tap * CC + o) * CC + t] = (wc >= 0.f) ? (ushort_t)PONE : (ushort_t)NONE;
    }
    red[t] = absacc; __syncthreads();
    for (int s = 128; s > 0; s >>= 1) { if (t < s) red[t] += red[t + s]; __syncthreads(); }
    if (t == 0) g_alpha[o] = red[0] * (1.0f / 2304.0f);
}

// ---------------- 4) conv: fp16 mma.sync implicit GEMM, f16 acc, 2 CTAs/SM --------
// CTA: M=128 padded positions x N=256 cout, K=2304 (72 stages of 32 channels).
// Warp tile 64x64 (2x4 warp grid). smem/CTA: A 3x8KB at [0,24K), B 3x16KB at [24K,72K).
__global__ void __launch_bounds__(256, 2) k_conv() {
    extern __shared__ __align__(128) char sm[];
    uint32_t sbase = (uint32_t)__cvta_generic_to_shared(sm);
    int tid = threadIdx.x;
    int warp = tid >> 5, lane = tid & 31;
    int wm = warp & 1, wn = warp >> 1;                 // 2(M) x 4(N) warp grid, 64x64 tiles
    int img = blockIdx.x / TILES, tile = blockIdx.x % TILES;
    int q0 = tile * 128;

    // cp.async per-thread setup
    int ar = tid >> 1, acb = (tid & 1) * 2;            // A: row ar, chunks acb, acb+1
    const ushort_t* gA = g_xq + ((size_t)img * WPIX + q0 + ar) * CC + acb * 8;
    const ushort_t* gB = g_wq + (size_t)tid * CC;      // B: row tid, 4 chunks
    uint32_t adst0 = swz64(ar, acb), adst1 = swz64(ar, acb + 1);
    uint32_t bdst[4];
    #pragma unroll
    for (int j = 0; j < 4; j++) bdst[j] = 24576 + swz64(tid, j);

    auto issue = [&](int s) {
        int tap = s >> 3, kc = s & 7;
        int dh = tap / 3, dw = tap - dh * 3;
        int buf = s % 3;
        const ushort_t* a = gA + (dh * WP + dw) * CC + kc * 32;
        uint32_t ab = sbase + buf * 8192;
        cpa16(ab + adst0, a);
        cpa16(ab + adst1, a + 8);
        const ushort_t* b = gB + (size_t)tap * CC * CC + kc * 32;
        uint32_t bb = sbase + buf * 16384;
        #pragma unroll
        for (int j = 0; j < 4; j++) cpa16(bb + bdst[j], b + j * 8);
        asm volatile("cp.async.commit_group;" ::: "memory");
    };

    // ldmatrix per-thread bases (R5-proven fragment mapping, 64B rows)
    int t8 = lane >> 3, r8 = lane & 7;
    int rowA = wm * 64 + (t8 & 1) * 8 + r8;
    int rowB = wn * 64 + (t8 & 1) * 8 + r8;
    int chalf = t8 >> 1;
    uint32_t a0[2], b0[2];
    #pragma unroll
    for (int kk = 0; kk < 2; kk++) {
        a0[kk] = swz64(rowA, kk * 2 + chalf);
        b0[kk] = 24576 + swz64(rowB, kk * 2 + chalf);
    }

    unsigned acc[4][8][2];                             // f16x2 accumulators (exact)
    #pragma unroll
    for (int i = 0; i < 4; i++)
        #pragma unroll
        for (int j = 0; j < 8; j++)
            acc[i][j][0] = acc[i][j][1] = 0u;

    issue(0); issue(1);

    #pragma unroll 1
    for (int s = 0; s < KSTAGES; s++) {
        asm volatile("cp.async.wait_group 1;" ::: "memory");
        __syncthreads();
        if (s + 2 < KSTAGES) issue(s + 2);
        else asm volatile("cp.async.commit_group;" ::: "memory");

        int buf = s % 3;
        uint32_t Ab = sbase + buf * 8192;
        uint32_t Bb = sbase + buf * 16384;
        #pragma unroll
        for (int kk = 0; kk < 2; kk++) {
            unsigned af[4][4], bf[4][4];
            #pragma unroll
            for (int mt = 0; mt < 4; mt++)
                ldm4(Ab + a0[kk] + mt * 1024, af[mt][0], af[mt][1], af[mt][2], af[mt][3]);
            #pragma unroll
            for (int nb = 0; nb < 4; nb++)
                ldm4(Bb + b0[kk] + nb * 1024, bf[nb][0], bf[nb][1], bf[nb][2], bf[nb][3]);
            #pragma unroll
            for (int mt = 0; mt < 4; mt++)
                #pragma unroll
                for (int nb = 0; nb < 4; nb++) {
                    hmma16(acc[mt][2 * nb],     af[mt], bf[nb][0], bf[nb][2]);
                    hmma16(acc[mt][2 * nb + 1], af[mt], bf[nb][1], bf[nb][3]);
                }
        }
    }

    // ---------------- epilogue: unpack f16 -> f32 store + fused stats ----------------
    int g = lane >> 2, t4 = lane & 3;
    float* p1[4]; float* p2[4]; bool v1[4], v2[4];
    #pragma unroll
    for (int mt = 0; mt < 4; mt++) {
        int m = wm * 64 + mt * 16 + g;
        int q = q0 + m;
        int hh = q / WP, ww = q - hh * WP;
        v1[mt] = (hh < CH) && (ww < CW);
        p1[mt] = g_acc + ((size_t)((img * CH + (v1[mt] ? hh : 0)) * CW + (v1[mt] ? ww : 0))) * CC;
        int q2 = q + 8;
        int hh2 = q2 / WP, ww2 = q2 - hh2 * WP;
        v2[mt] = (hh2 < CH) && (ww2 < CW);
        p2[mt] = g_acc + ((size_t)((img * CH + (v2[mt] ? hh2 : 0)) * CW + (v2[mt] ? ww2 : 0))) * CC;
    }

    int* red_s = (int*)sm;            // [2][256] overlay on stage smem
    int* red_q = (int*)sm + 512;      // [2][256]

    #pragma unroll
    for (int nt = 0; nt < 8; nt++) {
        int n = wn * 64 + nt * 8 + t4 * 2;
        int s0 = 0, s1 = 0; unsigned u0 = 0, u1 = 0;
        #pragma unroll
        for (int mt = 0; mt < 4; mt++) {
            float2 f01 = __half22float2(*(const __half2*)&acc[mt][nt][0]);
            float2 f23 = __half22float2(*(const __half2*)&acc[mt][nt][1]);
            if (v1[mt]) {
                *(float2*)(p1[mt] + n) = f01;
                int i0 = (int)f01.x, i1 = (int)f01.y;
                s0 += i0; u0 += (unsigned)(i0 * i0);
                s1 += i1; u1 += (unsigned)(i1 * i1);
            }
            if (v2[mt]) {
                *(float2*)(p2[mt] + n) = f23;
                int i2 = (int)f23.x, i3 = (int)f23.y;
                s0 += i2; u0 += (unsigned)(i2 * i2);
                s1 += i3; u1 += (unsigned)(i3 * i3);
            }
        }
        #pragma unroll
        for (int off = 4; off < 32; off <<= 1) {
            s0 += __shfl_xor_sync(0xffffffffu, s0, off);
            s1 += __shfl_xor_sync(0xffffffffu, s1, off);
            u0 += __shfl_xor_sync(0xffffffffu, u0, off);
            u1 += __shfl_xor_sync(0xffffffffu, u1, off);
        }
        if (g == 0) {
            red_s[wm * 256 + n] = s0;      red_s[wm * 256 + n + 1] = s1;
            red_q[wm * 256 + n] = (int)u0; red_q[wm * 256 + n + 1] = (int)u1;
        }
    }
    __syncthreads();
    if (tid < 256) {
        long long ts = (long long)red_s[tid] + (long long)red_s[256 + tid];
        long long tq = (long long)(unsigned)red_q[tid] + (long long)(unsigned)red_q[256 + tid];
        atomicAdd((unsigned long long*)&g_sum[tid], (unsigned long long)ts);
        atomicAdd(&g_sumsq[tid], (unsigned long long)tq);
    }
}

// ---------------- 5) per-channel scale/shift ----------------
__global__ void k_finalize(const float* __restrict__ gamma, const float* __restrict__ beta) {
    int o = threadIdx.x;
    double N = (double)NPIX;
    double mean = (double)g_sum[o] / N;
    double ex2  = (double)g_sumsq[o] / N;
    double var  = ex2 - mean * mean;
    double a    = (double)g_alpha[o];
    double inv  = 1.0 / sqrt(a * a * var + 1e-5);
    double sc   = (double)gamma[o] * a * inv;
    g_scale[o] = (float)sc;
    g_shift[o] = (float)((double)beta[o] - sc * mean);
}

// ---------------- 6) affine + relu + NHWC -> NCHW ----------------
__global__ void k_epilogue(float* __restrict__ out) {
    __shared__ float tile[64][57];
    int bh = blockIdx.x, oc = blockIdx.y;
    int b = bh / CH, h = bh % CH;
    const float* accp = g_acc + (size_t)bh * CW * CC + oc * 64;
    int t = threadIdx.x;
    int ol = t & 63, wq = t >> 6;
    float sc = g_scale[oc * 64 + ol], sh = g_shift[oc * 64 + ol];
    for (int w = wq; w < CW; w += 4)
        tile[ol][w] = fmaxf(fmaf(sc, accp[(size_t)w * CC + ol], sh), 0.f);
    __syncthreads();
    float* op = out + ((size_t)(b * CC + oc * 64) * CH + h) * CW;
    for (int idx = t; idx < 64 * CW; idx += 256) {
        int o_l = idx / CW, w = idx - o_l * CW;
        op[(size_t)o_l * CH * CW + w] = tile[o_l][w];
    }
}

// ---------------- launch ----------------
extern "C" void kernel_launch(void* const* d_in, const int* in_sizes, int n_in,
                              void* d_out, int out_size) {
    (void)in_sizes; (void)n_in; (void)out_size;
    const float* x     = (const float*)d_in[0];
    const float* w     = (const float*)d_in[1];
    // d_in[2] = bias: cancels exactly under training-mode BN
    const float* gamma = (const float*)d_in[3];
    const float* beta  = (const float*)d_in[4];
    float* out = (float*)d_out;

    cudaFuncSetAttribute(k_conv, cudaFuncAttributeMaxDynamicSharedMemorySize, 73728);

    int zthreads = 228 * CB * 32 + 131072 / 8;
    k_zero_halo<<<(zthreads + 255) / 256, 256>>>();
    k_pack<<<dim3(CB * CH, 8), 256>>>(x);
    k_prep_weights<<<CC, 256>>>(w);
    k_conv<<<CB * TILES, 256, 73728>>>();            // 4th launch -> ncu capture slot
    k_finalize<<<1, 256>>>(gamma, beta);
    k_epilogue<<<dim3(CB * CH, 4), 256>>>(out);
}